// round 14
// baseline (speedup 1.0000x reference)
#include <cuda_runtime.h>
#include <cuda_pipeline.h>
#include <math.h>
#include <stdint.h>

#define NT 256
#define NTE 512
constexpr int NODES = 4 * 2048;

__device__ float g_hv[NODES * 148];
__device__ float g_sb[NODES * 100];
__device__ float g_vb[NODES * 108];

// ---------------- register-tiled GEMM, weights in SMEM ----------------------
template<int NTT,int COLS,int KD,int NROW,int NC,int ARS,int WSTR,bool INITF,bool BIASF,bool RELUF>
__device__ __forceinline__ void gemm_rt(
    const float* __restrict__ A, const float* __restrict__ W,
    const float* __restrict__ initv, const float* __restrict__ bias,
    float* __restrict__ O, const int tid)
{
  constexpr int GPC = NROW / 4;
  constexpr int G   = NC * GPC;
  constexpr int TPG = COLS / 4;
  const int eg = (tid & (TPG - 1)) * 4;
  for (int g = tid / TPG; g < G; g += NTT / TPG) {
    const int c  = g / GPC;
    const int rg = (g - c * GPC) * 4;
    float4 a0, a1, a2, a3;
    if (INITF) {
      const float* iv = initv + c * NROW + rg;
      a0 = make_float4(iv[0], iv[0], iv[0], iv[0]);
      a1 = make_float4(iv[1], iv[1], iv[1], iv[1]);
      a2 = make_float4(iv[2], iv[2], iv[2], iv[2]);
      a3 = make_float4(iv[3], iv[3], iv[3], iv[3]);
    } else {
      a0 = make_float4(0.f,0.f,0.f,0.f); a1 = a0; a2 = a0; a3 = a0;
    }
    const float* ap = A + (size_t)(c * ARS) * COLS + eg;
    const float* wp = W + rg;
    #pragma unroll 4
    for (int k = 0; k < KD; ++k) {
      const float4 av = *(const float4*)(ap + (size_t)k * COLS);
      const float4 wv4 = *(const float4*)(wp + (size_t)k * WSTR);
      a0.x += wv4.x*av.x; a0.y += wv4.x*av.y; a0.z += wv4.x*av.z; a0.w += wv4.x*av.w;
      a1.x += wv4.y*av.x; a1.y += wv4.y*av.y; a1.z += wv4.y*av.z; a1.w += wv4.y*av.w;
      a2.x += wv4.z*av.x; a2.y += wv4.z*av.y; a2.z += wv4.z*av.z; a2.w += wv4.z*av.w;
      a3.x += wv4.w*av.x; a3.y += wv4.w*av.y; a3.z += wv4.w*av.z; a3.w += wv4.w*av.w;
    }
    if (BIASF) {
      const float* bp = bias + c * NROW + rg;
      float b0=bp[0], b1=bp[1], b2=bp[2], b3=bp[3];
      a0.x+=b0; a0.y+=b0; a0.z+=b0; a0.w+=b0;
      a1.x+=b1; a1.y+=b1; a1.z+=b1; a1.w+=b1;
      a2.x+=b2; a2.y+=b2; a2.z+=b2; a2.w+=b2;
      a3.x+=b3; a3.y+=b3; a3.z+=b3; a3.w+=b3;
    }
    if (RELUF) {
      a0.x=fmaxf(a0.x,0.f); a0.y=fmaxf(a0.y,0.f); a0.z=fmaxf(a0.z,0.f); a0.w=fmaxf(a0.w,0.f);
      a1.x=fmaxf(a1.x,0.f); a1.y=fmaxf(a1.y,0.f); a1.z=fmaxf(a1.z,0.f); a1.w=fmaxf(a1.w,0.f);
      a2.x=fmaxf(a2.x,0.f); a2.y=fmaxf(a2.y,0.f); a2.z=fmaxf(a2.z,0.f); a2.w=fmaxf(a2.w,0.f);
      a3.x=fmaxf(a3.x,0.f); a3.y=fmaxf(a3.y,0.f); a3.z=fmaxf(a3.z,0.f); a3.w=fmaxf(a3.w,0.f);
    }
    float* op = O + (size_t)(c * NROW + rg) * COLS + eg;
    *(float4*)(op)          = a0;
    *(float4*)(op + COLS)   = a1;
    *(float4*)(op + 2*COLS) = a2;
    *(float4*)(op + 3*COLS) = a3;
  }
}

// -------------------- tf32 mma helpers -------------------------------------
__device__ __forceinline__ uint32_t f2tf(float x){
  uint32_t r; asm("cvt.rna.tf32.f32 %0, %1;" : "=r"(r) : "f"(x)); return r;
}
__device__ __forceinline__ void mma8(float* c, uint32_t a0,uint32_t a1,uint32_t a2,uint32_t a3,
                                     uint32_t b0,uint32_t b1){
  asm volatile("mma.sync.aligned.m16n8k8.row.col.f32.tf32.tf32.f32 "
    "{%0,%1,%2,%3}, {%4,%5,%6,%7}, {%8,%9}, {%0,%1,%2,%3};"
    : "+f"(c[0]),"+f"(c[1]),"+f"(c[2]),"+f"(c[3])
    : "r"(a0),"r"(a1),"r"(a2),"r"(a3),"r"(b0),"r"(b1));
}

// tf32 MMA GEMM, N=100: C^T[M][100] = As[M][KPAD] * W[KREAL][100]
// cp.async double-buffered weight staging (pad rows zero-filled). One sync/chunk.
template<int NTT,int NQ,int KPAD,int KREAL,int CH,int ASTR,int OSTR,int WSRC,int ISTR,bool INITF,bool RELUF>
__device__ __forceinline__ void gemm_mma(
    const float* __restrict__ As, const float* __restrict__ Wg,
    const float* __restrict__ initv, const float* __restrict__ bias,
    float* __restrict__ OT, float* __restrict__ wbuf, const int tid)
{
  constexpr int WS  = 104;
  constexpr int NCH = KPAD / CH;
  constexpr int T   = 13;
  constexpr int JMAX = (T + NQ - 1) / NQ;
  static_assert(KPAD % CH == 0 && CH % 8 == 0, "pad");
  const int lane = tid & 31;
  const int warp = tid >> 5;
  const int g  = lane >> 2;
  const int tq = lane & 3;
  const int mt = warp / NQ;
  const int q  = warp % NQ;
  float acc[JMAX][4];
  #pragma unroll
  for (int j=0;j<JMAX;++j){acc[j][0]=0.f;acc[j][1]=0.f;acc[j][2]=0.f;acc[j][3]=0.f;}

  auto stage = [&](int ch){
    float* db = wbuf + (ch & 1) * (CH * WS);
    const int base = ch * CH;
    for (int i = tid; i < CH*25; i += NTT) {
      int r = i / 25, c4 = i - r*25;
      int kr = base + r;
      if (kr < KREAL) __pipeline_memcpy_async(db + r*WS + c4*4, Wg + (size_t)kr*WSRC + c4*4, 16);
      else { float4 z = make_float4(0.f,0.f,0.f,0.f); *(float4*)(db + r*WS + c4*4) = z; }
    }
    __pipeline_commit();
  };
  stage(0);
  for (int ch = 0; ch < NCH; ++ch) {
    __pipeline_wait_prior(0);
    __syncthreads();
    if (ch + 1 < NCH) stage(ch + 1);
    const float* wb = wbuf + (ch & 1) * (CH * WS);
    const float* arow = As + (size_t)(mt*16 + g) * ASTR + ch*CH;
    #pragma unroll
    for (int k8 = 0; k8 < CH/8; ++k8) {
      const float* ar = arow + k8*8;
      uint32_t a0 = f2tf(ar[tq]);
      uint32_t a1 = f2tf(ar[8*ASTR + tq]);
      uint32_t a2 = f2tf(ar[tq + 4]);
      uint32_t a3 = f2tf(ar[8*ASTR + tq + 4]);
      const float* wrow = wb + (k8*8 + tq)*WS + g;
      #pragma unroll
      for (int j = 0; j < JMAX; ++j) {
        int tile = q + NQ*j;
        if (tile < T) {
          const float* wr = wrow + tile*8;
          uint32_t b0 = f2tf(wr[0]);
          uint32_t b1 = f2tf(wr[4*WS]);
          mma8(acc[j], a0,a1,a2,a3, b0,b1);
        }
      }
    }
  }
  const int e0 = mt*16 + g;
  const float* iv = INITF ? (initv + (e0 >> 5) * ISTR) : nullptr;
  #pragma unroll
  for (int j = 0; j < JMAX; ++j) {
    int tile = q + NQ*j;
    if (tile < T) {
      int mb = tile*8 + 2*tq;
      #pragma unroll
      for (int hf = 0; hf < 2; ++hf) {
        int m = mb + hf;
        if (m < 100) {
          float add = (INITF ? iv[m] : 0.f) + bias[m];
          float v0 = acc[j][hf]   + add;
          float v1 = acc[j][2+hf] + add;
          if (RELUF) { v0 = fmaxf(v0, 0.f); v1 = fmaxf(v1, 0.f); }
          OT[(size_t)e0 * OSTR + m]     = v0;
          OT[(size_t)(e0+8) * OSTR + m] = v1;
        }
      }
    }
  }
}

// tf32 MMA, N=100, weights PERSISTENT in SMEM [KPAD][WS] (pads zeroed).
// NO internal syncs: caller must __syncthreads() before (A & W ready) and after.
template<int NTT,int NQ,int KPAD,int ASTR,int OSTR,int WS,bool RELUF>
__device__ __forceinline__ void gemm_mmaP(
    const float* __restrict__ As, const float* __restrict__ W,
    const float* __restrict__ bias, float* __restrict__ OT, const int tid)
{
  constexpr int T   = 13;
  constexpr int JMAX = (T + NQ - 1) / NQ;
  const int lane = tid & 31;
  const int warp = tid >> 5;
  const int g  = lane >> 2;
  const int tq = lane & 3;
  const int mt = warp / NQ;
  const int q  = warp % NQ;
  float acc[JMAX][4];
  #pragma unroll
  for (int j=0;j<JMAX;++j){acc[j][0]=0.f;acc[j][1]=0.f;acc[j][2]=0.f;acc[j][3]=0.f;}
  const float* arow = As + (size_t)(mt*16 + g) * ASTR;
  #pragma unroll 4
  for (int k8 = 0; k8 < KPAD/8; ++k8) {
    const float* ar = arow + k8*8;
    uint32_t a0 = f2tf(ar[tq]);
    uint32_t a1 = f2tf(ar[8*ASTR + tq]);
    uint32_t a2 = f2tf(ar[tq + 4]);
    uint32_t a3 = f2tf(ar[8*ASTR + tq + 4]);
    const float* wrow = W + (k8*8 + tq)*WS + g;
    #pragma unroll
    for (int j = 0; j < JMAX; ++j) {
      int tile = q + NQ*j;
      if (tile < T) {
        const float* wr = wrow + tile*8;
        uint32_t b0 = f2tf(wr[0]);
        uint32_t b1 = f2tf(wr[4*WS]);
        mma8(acc[j], a0,a1,a2,a3, b0,b1);
      }
    }
  }
  const int e0 = mt*16 + g;
  #pragma unroll
  for (int j = 0; j < JMAX; ++j) {
    int tile = q + NQ*j;
    if (tile < T) {
      int mb = tile*8 + 2*tq;
      #pragma unroll
      for (int hf = 0; hf < 2; ++hf) {
        int m = mb + hf;
        if (m < 100) {
          float v0 = acc[j][hf]   + bias[m];
          float v1 = acc[j][2+hf] + bias[m];
          if (RELUF) { v0 = fmaxf(v0, 0.f); v1 = fmaxf(v1, 0.f); }
          OT[(size_t)e0 * OSTR + m]     = v0;
          OT[(size_t)(e0+8) * OSTR + m] = v1;
        }
      }
    }
  }
}

// tf32 MMA GEMM, wide N (cp.async staged)
template<int NTT,int NQ,int KPAD,int KREAL,int CH,int ASTR,int OSTR,int N,bool RELUF>
__device__ __forceinline__ void gemm_mmaW(
    const float* __restrict__ As, const float* __restrict__ Wg,
    const float* __restrict__ bias,
    float* __restrict__ OT, float* __restrict__ wbuf, const int tid)
{
  constexpr int WS  = N + 8;
  constexpr int NCH = KPAD / CH;
  constexpr int T   = N / 8;
  constexpr int JMAX = (T + NQ - 1) / NQ;
  static_assert(KPAD % CH == 0 && CH % 8 == 0 && N % 8 == 0, "pad");
  const int lane = tid & 31;
  const int warp = tid >> 5;
  const int g  = lane >> 2;
  const int tq = lane & 3;
  const int mt = warp / NQ;
  const int q  = warp % NQ;
  float acc[JMAX][4];
  #pragma unroll
  for (int j=0;j<JMAX;++j){acc[j][0]=0.f;acc[j][1]=0.f;acc[j][2]=0.f;acc[j][3]=0.f;}

  auto stage = [&](int ch){
    float* db = wbuf + (ch & 1) * (CH * WS);
    const int base = ch * CH;
    constexpr int Q4 = N / 4;
    for (int i = tid; i < CH*Q4; i += NTT) {
      int r = i / Q4, c4 = i - r*Q4;
      int kr = base + r;
      if (kr < KREAL) __pipeline_memcpy_async(db + r*WS + c4*4, Wg + (size_t)kr*N + c4*4, 16);
      else { float4 z = make_float4(0.f,0.f,0.f,0.f); *(float4*)(db + r*WS + c4*4) = z; }
    }
    __pipeline_commit();
  };
  stage(0);
  for (int ch = 0; ch < NCH; ++ch) {
    __pipeline_wait_prior(0);
    __syncthreads();
    if (ch + 1 < NCH) stage(ch + 1);
    const float* wb = wbuf + (ch & 1) * (CH * WS);
    const float* arow = As + (size_t)(mt*16 + g) * ASTR + ch*CH;
    #pragma unroll
    for (int k8 = 0; k8 < CH/8; ++k8) {
      const float* ar = arow + k8*8;
      uint32_t a0 = f2tf(ar[tq]);
      uint32_t a1 = f2tf(ar[8*ASTR + tq]);
      uint32_t a2 = f2tf(ar[tq + 4]);
      uint32_t a3 = f2tf(ar[8*ASTR + tq + 4]);
      const float* wrow = wb + (k8*8 + tq)*WS + g;
      #pragma unroll
      for (int j = 0; j < JMAX; ++j) {
        int tile = q + NQ*j;
        if (tile < T) {
          const float* wr = wrow + tile*8;
          uint32_t b0 = f2tf(wr[0]);
          uint32_t b1 = f2tf(wr[4*WS]);
          mma8(acc[j], a0,a1,a2,a3, b0,b1);
        }
      }
    }
  }
  const int e0 = mt*16 + g;
  #pragma unroll
  for (int j = 0; j < JMAX; ++j) {
    int tile = q + NQ*j;
    if (tile < T) {
      int mb = tile*8 + 2*tq;
      #pragma unroll
      for (int hf = 0; hf < 2; ++hf) {
        int m = mb + hf;
        float b = bias[m];
        float v0 = acc[j][hf]   + b;
        float v1 = acc[j][2+hf] + b;
        if (RELUF) { v0 = fmaxf(v0, 0.f); v1 = fmaxf(v1, 0.f); }
        OT[(size_t)e0 * OSTR + m]     = v0;
        OT[(size_t)(e0+8) * OSTR + m] = v1;
      }
    }
  }
}

// ------------ K0: hoisted per-node partials (32-node MMA tiles) -------------
__global__ __launch_bounds__(NT)
void k_pre(const float* __restrict__ hV,
           const float* __restrict__ ws1, const float* __restrict__ wh1)
{
  extern __shared__ float sm[];
  float* As  = sm;            // [32][108]
  float* WB  = As + 3456;     // wbuf
  float* WH  = WB + 10816;    // 528
  float* HVv = WH + 528;      // [32][48]
  float* ZB  = HVv + 1536;    // 104
  const int tid = threadIdx.x;
  const int n0 = blockIdx.x * 32;

  for (int i = tid; i < 528; i += NT) WH[i] = wh1[i];
  for (int i = tid; i < 104; i += NT) ZB[i] = 0.f;
  for (int idx = tid; idx < 32 * 8; idx += NT) {
    int e = idx >> 3, j = idx & 7;
    As[e * 108 + 100 + j] = 0.f;
  }
  for (int idx = tid; idx < 32 * 148; idx += NT) {
    int e = idx / 148, r = idx - e * 148;
    float v = hV[(size_t)(n0 + e) * 148 + r];
    if (r < 48) HVv[e * 48 + r] = v;
    else        As[e * 108 + (r - 48)] = v;
  }
  __syncthreads();
  gemm_mma<NT,4,104,100,104,108,100,100,0,false,false>(
      As, ws1, nullptr, ZB, g_sb + (size_t)n0 * 100, WB, tid);
  for (int t = tid; t < 32 * 108; t += NT) {
    int e = t / 108, u = t - e * 108;
    int c = u / 36, h = u - c * 36;
    float acc = 0.f;
    if (h < 33) {
      #pragma unroll
      for (int i = 0; i < 16; ++i) acc += HVv[e * 48 + c * 16 + i] * WH[i * 33 + h];
    }
    g_vb[(size_t)(n0 + e) * 108 + u] = acc;
  }
}

// --------------- K1: edges + mean + LN1 (node PAIRS, 64-edge tiles) --------
#define O_WH1P 0
#define O_WV1  1188
#define O_BS1  1716
#define O_WH2  1816
#define O_WV2  2072
#define O_BS2  2328
#define O_WH3  2428
#define O_WV3  2684
#define O_BS3  2940
#define O_LG1  3040
#define O_LB1  3140
#define O_HS   3240   /* 296 */
#define O_MK   3536   /* 64 */
#define O_SB   3600   /* 200 */
#define O_VB   3800   /* 216 */
#define O_VC1  4016   /* 51*64 = 3264 */
#define O_SC1T 7280   /* [64][172] = 11008 */
#define O_VHX  18288  /* [108][64] = 6912 ; EBV alias */
#define O_BFAT 25200  /* [64][124] = 7936 */
#define O_VOA  33136  /* [48][64] = 3072 */
#define O_DH   36208  /* 296 */
#define O_MISC 36504  /* 16 */
#define O_WBUF 36520  /* 2*24*104 = 4992 */
#define O_WS3P 41512  /* [120][104] = 12480 */
#define SM1_FLOATS 53992

__global__ __launch_bounds__(NTE, 1)
void k_edge(const float* __restrict__ hV, const float* __restrict__ hM,
            const int* __restrict__ maskA,
            const float* __restrict__ wh1, const float* __restrict__ ws1,
            const float* __restrict__ bs1, const float* __restrict__ wv1,
            const float* __restrict__ wh2, const float* __restrict__ ws2,
            const float* __restrict__ bs2, const float* __restrict__ wv2,
            const float* __restrict__ wh3, const float* __restrict__ ws3,
            const float* __restrict__ bs3, const float* __restrict__ wv3,
            const float* __restrict__ ln1g, const float* __restrict__ ln1b)
{
  extern __shared__ float sm[];
  float* WH1P = sm + O_WH1P;
  float* WV1  = sm + O_WV1;
  float* BS1s = sm + O_BS1;
  float* WH2s = sm + O_WH2;
  float* WV2s = sm + O_WV2;
  float* BS2s = sm + O_BS2;
  float* WH3s = sm + O_WH3;
  float* WV3s = sm + O_WV3;
  float* BS3s = sm + O_BS3;
  float* LG1  = sm + O_LG1;
  float* LB1  = sm + O_LB1;
  float* HS   = sm + O_HS;
  float* MK   = sm + O_MK;
  float* SB   = sm + O_SB;
  float* VB   = sm + O_VB;
  float* VC1  = sm + O_VC1;
  float* SC1T = sm + O_SC1T;
  float* VHX  = sm + O_VHX;
  float* BFAT = sm + O_BFAT;
  float* BFBT = sm + O_SC1T;   // alias
  float* VOA  = sm + O_VOA;
  float* DH   = sm + O_DH;
  float* MISC = sm + O_MISC;
  float* WBUF = sm + O_WBUF;
  float* WS3P = sm + O_WS3P;
  float* EBV  = sm + O_VHX;    // vector staging [2][30][51] = 3060 (fits VHX)
  const int tid = threadIdx.x;

  for (int i = tid; i < 1188; i += NTE) { int r = i / 36, c = i - r * 36; WH1P[i] = (c < 33) ? wh1[r * 33 + c] : 0.f; }
  for (int i = tid; i < 528;  i += NTE) WV1[i]  = wv1[i];
  for (int i = tid; i < 100;  i += NTE) { BS1s[i] = bs1[i]; BS2s[i] = bs2[i]; BS3s[i] = bs3[i]; LG1[i] = ln1g[i]; LB1[i] = ln1b[i]; }
  for (int i = tid; i < 256;  i += NTE) { WH2s[i] = wh2[i]; WV2s[i] = wv2[i]; WH3s[i] = wh3[i]; WV3s[i] = wv3[i]; }
  // persistent ws3: [120][104], real rows/cols from ws3, pads zero
  for (int i = tid; i < 12480; i += NTE) {
    int r = i / 104, c = i - r * 104;
    WS3P[i] = (r < 116 && c < 100) ? ws3[r * 100 + c] : 0.f;
  }
  for (int i = tid; i < 3264;  i += NTE) VC1[i]  = 0.f;
  for (int i = tid; i < 11008; i += NTE) SC1T[i] = 0.f;
  for (int i = tid; i < 7936;  i += NTE) BFAT[i] = 0.f;
  for (int i = tid; i < 4992;  i += NTE) WBUF[i] = 0.f;
  __syncthreads();

  for (int pair = blockIdx.x; pair < NODES / 2; pair += gridDim.x) {
    const float* mp = hM + (size_t)pair * 10980;
    for (int idx = tid; idx < 2 * 30 * 132; idx += NTE) {
      int n = idx / 3960, rem = idx - n * 3960;
      int e = rem / 132, j = rem - e * 132;
      SC1T[(size_t)(n * 32 + e) * 172 + j] = mp[n * 5490 + e * 183 + 51 + j];
    }
    for (int idx = tid; idx < 2 * 30 * 51; idx += NTE) {
      int n = idx / 1530, rem = idx - n * 1530;
      EBV[idx] = mp[n * 5490 + (rem / 51) * 183 + (rem % 51)];
    }
    for (int t = tid; t < 296; t += NTE) HS[t] = hV[(size_t)pair * 296 + t];
    for (int t = tid; t < 200; t += NTE) SB[t] = g_sb[(size_t)pair * 200 + t];
    for (int t = tid; t < 216; t += NTE) VB[t] = g_vb[(size_t)pair * 216 + t];
    for (int t = tid; t < 64;  t += NTE) {
      int el = t & 31;
      MK[t] = (el < 30) ? (float)maskA[(size_t)(2 * pair + (t >> 5)) * 30 + el] : 0.f;
    }
    __syncthreads();
    for (int idx = tid; idx < 51 * 64; idx += NTE) {
      int j = idx >> 6, e = idx & 63;
      int n = e >> 5, el = e & 31;
      if (el < 30) VC1[j * 64 + e] = EBV[n * 1530 + el * 51 + j];
    }
    __syncthreads();
    gemm_rt<NTE,64,17,36,3,17,36,false,false,false>(VC1, WH1P + 16 * 36, nullptr, nullptr, VHX, tid);
    __syncthreads();
    for (int idx = tid; idx < 108 * 64; idx += NTE) {
      int r = idx >> 6, e = idx & 63;
      VHX[idx] += VB[(e >> 5) * 108 + r];
    }
    __syncthreads();
    for (int t = tid; t < 33 * 64; t += NTE) {
      int h = t >> 6, e = t & 63;
      float a = VHX[h*64+e], b = VHX[(36+h)*64+e], c2 = VHX[(72+h)*64+e];
      SC1T[(size_t)e * 172 + 132 + h] = sqrtf(fmaxf(a*a + b*b + c2*c2, 1e-8f));
    }
    gemm_rt<NTE,64,33,16,3,36,16,false,false,false>(VHX, WV1, nullptr, nullptr, VOA, tid);
    gemm_mma<NTE,4,168,165,24,172,124,100,100,true,true>(SC1T, ws1 + 10000, SB, BS1s, BFAT, WBUF, tid);
    for (int t = tid; t < 16 * 64; t += NTE) {
      int o = t >> 6, e = t & 63;
      float a = VOA[o*64+e], b = VOA[(16+o)*64+e], c2 = VOA[(32+o)*64+e];
      float n = sqrtf(fmaxf(a*a + b*b + c2*c2, 1e-8f));
      float gt = 1.f / (1.f + expf(-n));
      VOA[o*64+e] = a*gt; VOA[(16+o)*64+e] = b*gt; VOA[(32+o)*64+e] = c2*gt;
    }
    __syncthreads();
    gemm_rt<NTE,64,16,16,3,16,16,false,false,false>(VOA, WH2s, nullptr, nullptr, VHX, tid);
    __syncthreads();
    for (int t = tid; t < 16 * 64; t += NTE) {
      int h = t >> 6, e = t & 63;
      float a = VHX[h*64+e], b = VHX[(16+h)*64+e], c2 = VHX[(32+h)*64+e];
      BFAT[(size_t)e * 124 + 100 + h] = sqrtf(fmaxf(a*a + b*b + c2*c2, 1e-8f));
    }
    gemm_rt<NTE,64,16,16,3,16,16,false,false,false>(VHX, WV2s, nullptr, nullptr, VOA, tid);
    gemm_mma<NTE,4,120,116,24,124,124,100,0,false,true>(BFAT, ws2, nullptr, BS2s, BFBT, WBUF, tid);
    for (int t = tid; t < 16 * 64; t += NTE) {
      int o = t >> 6, e = t & 63;
      float a = VOA[o*64+e], b = VOA[(16+o)*64+e], c2 = VOA[(32+o)*64+e];
      float n = sqrtf(fmaxf(a*a + b*b + c2*c2, 1e-8f));
      float gt = 1.f / (1.f + expf(-n));
      VOA[o*64+e] = a*gt; VOA[(16+o)*64+e] = b*gt; VOA[(32+o)*64+e] = c2*gt;
    }
    __syncthreads();
    gemm_rt<NTE,64,16,16,3,16,16,false,false,false>(VOA, WH3s, nullptr, nullptr, VHX, tid);
    __syncthreads();
    for (int t = tid; t < 16 * 64; t += NTE) {
      int h = t >> 6, e = t & 63;
      float a = VHX[h*64+e], b = VHX[(16+h)*64+e], c2 = VHX[(32+h)*64+e];
      BFBT[(size_t)e * 124 + 100 + h] = sqrtf(fmaxf(a*a + b*b + c2*c2, 1e-8f));
    }
    gemm_rt<NTE,64,16,16,3,16,16,false,false,false>(VHX, WV3s, nullptr, nullptr, VOA, tid);
    __syncthreads();   // BFBT (vn3) and VOA ready before syncless persistent-W GEMM
    gemm_mmaP<NTE,4,120,124,124,104,false>(BFBT, WS3P, BS3s, BFAT, tid);
    __syncthreads();
    for (int t = tid; t < 296; t += NTE) {
      int n = t / 148, r = t - n * 148;
      float acc = 0.f;
      if (r < 48) {
        #pragma unroll
        for (int ee = 0; ee < 32; ++ee) {
          int e = n * 32 + ((ee + r) & 31);
          acc += MK[e] * VOA[r * 64 + e];
        }
      } else {
        int rr = r - 48;
        #pragma unroll 6
        for (int e = 0; e < 30; ++e) acc += MK[n * 32 + e] * BFAT[(size_t)(n * 32 + e) * 124 + rr];
      }
      DH[t] = HS[t] + acc * (1.f / 30.f);
    }
    __syncthreads();
    if (tid < 64) {
      const int w = tid >> 5, lane = tid & 31;
      const float* D = DH + w * 148;
      float vm = 0.f;
      if (lane < 16) { float a = D[lane], b = D[16+lane], c2 = D[32+lane]; vm = fmaxf(a*a + b*b + c2*c2, 1e-8f); }
      #pragma unroll
      for (int o = 16; o; o >>= 1) vm += __shfl_xor_sync(0xffffffffu, vm, o);
      float s0 = D[48+lane], s1 = D[80+lane], s2v = D[112+lane];
      float s3v = (lane < 4) ? D[144+lane] : 0.f;
      float p = s0 + s1 + s2v + s3v;
      #pragma unroll
      for (int o = 16; o; o >>= 1) p += __shfl_xor_sync(0xffffffffu, p, o);
      float mu = p * 0.01f;
      float d0 = s0-mu, d1 = s1-mu, d2 = s2v-mu;
      float q = d0*d0 + d1*d1 + d2*d2;
      if (lane < 4) { float d3 = s3v - mu; q += d3*d3; }
      #pragma unroll
      for (int o = 16; o; o >>= 1) q += __shfl_xor_sync(0xffffffffu, q, o);
      if (lane == 0) {
        MISC[w*4+0] = rsqrtf(vm * (1.f/16.f));
        MISC[w*4+1] = mu;
        MISC[w*4+2] = rsqrtf(q * 0.01f + 1e-3f);
      }
    }
    __syncthreads();
    for (int t = tid; t < 296; t += NTE) {
      int n = t / 148, r = t - n * 148;
      float v = DH[t];
      if (r < 48) v = v * MISC[n*4];
      else { int j = r - 48; v = (v - MISC[n*4+1]) * MISC[n*4+2] * LG1[j] + LB1[j]; }
      g_hv[(size_t)pair * 296 + t] = v;
    }
    __syncthreads();
  }
}

// -------------------- K2: fused dh1+dh2+LN2 (16-node tiles, 512 thr) -------
#define DHT 512
__global__ __launch_bounds__(DHT, 2)
void k_dh(const float* __restrict__ wh1, const float* __restrict__ ws1g,
          const float* __restrict__ bs1, const float* __restrict__ wv1,
          const float* __restrict__ wh2, const float* __restrict__ ws2g,
          const float* __restrict__ bs2, const float* __restrict__ wv2,
          const float* __restrict__ ln2g, const float* __restrict__ ln2b,
          const int* __restrict__ maskV, float* __restrict__ out)
{
  extern __shared__ float sm[];
  float* WHs1 = sm;             // 512
  float* WVs1 = WHs1 + 512;     // 1024
  float* BSs1 = WVs1 + 1024;    // 400
  float* WHs2 = BSs1 + 400;     // 1024
  float* WVs2 = WHs2 + 1024;    // 512
  float* BSs2 = WVs2 + 512;     // 100
  float* VC1  = BSs2 + 100;     // 768
  float* SC1T = VC1 + 768;      // 2368
  float* VH   = SC1T + 2368;    // 1536
  float* VOd1 = VH + 1536;      // 1536
  float* SCT  = VOd1 + 1536;    // 6976
  float* VO2  = SCT + 6976;     // 768
  float* OT   = VO2 + 768;      // 1664
  float* ST   = OT + 1664;      // 80
  float* WBUF = ST + 80;        // 6528
  float* RES  = WBUF;           // [148][17] alias after MMAs done
  const int tid = threadIdx.x;
  const int n0 = blockIdx.x * 16;

  for (int i = tid; i < 512;  i += DHT) WHs1[i] = wh1[i];
  for (int i = tid; i < 1024; i += DHT) WVs1[i] = wv1[i];
  for (int i = tid; i < 400;  i += DHT) BSs1[i] = bs1[i];
  for (int i = tid; i < 1024; i += DHT) WHs2[i] = wh2[i];
  for (int i = tid; i < 512;  i += DHT) WVs2[i] = wv2[i];
  for (int i = tid; i < 100;  i += DHT) BSs2[i] = bs2[i];
  if (tid < 16) ST[48 + tid] = (float)maskV[n0 + tid];
  for (int idx = tid; idx < 48 * 16; idx += DHT) {
    int r = idx >> 4, e = idx & 15;
    VC1[r * 16 + e] = g_hv[(size_t)(n0 + e) * 148 + r];
  }
  for (int idx = tid; idx < 16 * 148; idx += DHT) {
    int e = idx / 148, j = idx - e * 148;
    SC1T[idx] = (j < 100) ? g_hv[(size_t)(n0 + e) * 148 + 48 + j] : 0.f;
  }
  __syncthreads();
  gemm_rt<DHT,16,16,32,3,16,32,false,false,false>(VC1, WHs1, nullptr, nullptr, VH, tid);
  __syncthreads();
  {
    int h = tid >> 4, e = tid & 15;
    float a = VH[h*16+e], b = VH[(32+h)*16+e], c2 = VH[(64+h)*16+e];
    SC1T[e * 148 + 100 + h] = sqrtf(fmaxf(a*a + b*b + c2*c2, 1e-8f));
  }
  gemm_rt<DHT,16,32,32,3,32,32,false,false,false>(VH, WVs1, nullptr, nullptr, VOd1, tid);
  gemm_mmaW<DHT,16,144,132,8,148,436,400,true>(SC1T, ws1g, BSs1, SCT, WBUF, tid);
  __syncthreads();
  {
    int o = tid >> 4, e = tid & 15;
    float a = VOd1[o*16+e], b = VOd1[(32+o)*16+e], c2 = VOd1[(64+o)*16+e];
    float n = sqrtf(fmaxf(a*a + b*b + c2*c2, 1e-8f));
    float gt = 1.f / (1.f + expf(-n));
    VOd1[o*16+e] = a*gt; VOd1[(32+o)*16+e] = b*gt; VOd1[(64+o)*16+e] = c2*gt;
  }
  __syncthreads();
  gemm_rt<DHT,16,32,32,3,32,32,false,false,false>(VOd1, WHs2, nullptr, nullptr, VH, tid);
  __syncthreads();
  {
    int h = tid >> 4, e = tid & 15;
    float a = VH[h*16+e], b = VH[(32+h)*16+e], c2 = VH[(64+h)*16+e];
    SCT[e * 436 + 400 + h] = sqrtf(fmaxf(a*a + b*b + c2*c2, 1e-8f));
  }
  gemm_rt<DHT,16,32,16,3,32,16,false,false,false>(VH, WVs2, nullptr, nullptr, VO2, tid);
  gemm_mma<DHT,16,432,432,24,436,104,100,0,false,false>(SCT, ws2g, nullptr, BSs2, OT, WBUF, tid);
  __syncthreads();
  for (int idx = tid; idx < 148 * 16; idx += DHT) {
    int r = idx >> 4, e = idx & 15;
    float add = (r < 48) ? VO2[r * 16 + e] : OT[e * 104 + (r - 48)];
    RES[r * 17 + e] = g_hv[(size_t)(n0 + e) * 148 + r] + add;
  }
  __syncthreads();
  if (tid < 16) {
    const int e = tid;
    float vm = 0.f;
    #pragma unroll
    for (int i = 0; i < 16; ++i) {
      float a = RES[i*17+e], b = RES[(16+i)*17+e], c2 = RES[(32+i)*17+e];
      vm += fmaxf(a*a + b*b + c2*c2, 1e-8f);
    }
    float mu = 0.f;
    #pragma unroll 4
    for (int j = 0; j < 100; ++j) mu += RES[(48+j)*17+e];
    mu *= 0.01f;
    float var = 0.f;
    #pragma unroll 4
    for (int j = 0; j < 100; ++j) { float d = RES[(48+j)*17+e] - mu; var += d*d; }
    var *= 0.01f;
    ST[e]    = rsqrtf(vm * (1.f/16.f));
    ST[16+e] = mu;
    ST[32+e] = rsqrtf(var + 1e-3f);
  }
  __syncthreads();
  for (int idx = tid; idx < 16 * 148; idx += DHT) {
    int e = idx / 148, r = idx - e * 148;
    float v = RES[r * 17 + e];
    if (r < 48) v = v * ST[e];
    else { int j = r - 48; v = (v - ST[16+e]) * ST[32+e] * ln2g[j] + ln2b[j]; }
    out[(size_t)(n0 + e) * 148 + r] = ST[48 + e] * v;
  }
}

// ---------------------------------------------------------------------------
extern "C" void kernel_launch(void* const* d_in, const int* in_sizes, int n_in,
                              void* d_out, int out_size)
{
  const float* hV      = (const float*)d_in[0];
  const float* hM      = (const float*)d_in[1];
  const int*   maskV   = (const int*)  d_in[2];
  const int*   maskA   = (const int*)  d_in[3];
  const float* wev1_wh = (const float*)d_in[4];
  const float* wev1_ws = (const float*)d_in[5];
  const float* wev1_bs = (const float*)d_in[6];
  const float* wev1_wv = (const float*)d_in[7];
  const float* wev2_wh = (const float*)d_in[8];
  const float* wev2_ws = (const float*)d_in[9];
  const float* wev2_bs = (const float*)d_in[10];
  const float* wev2_wv = (const float*)d_in[11];
  const float* wev3_wh = (const float*)d_in[12];
  const float* wev3_ws = (const float*)d_in[13];
  const float* wev3_bs = (const float*)d_in[14];
  const float* wev3_wv = (const float*)d_in[15];
  const float* wdh1_wh = (const float*)d_in[16];
  const float* wdh1_ws = (const float*)d_in[17];
  const float* wdh1_bs = (const float*)d_in[18];
  const float* wdh1_wv = (const float*)d_in[19];
  const float* wdh2_wh = (const float*)d_in[20];
  const float* wdh2_ws = (const float*)d_in[21];
  const float* wdh2_bs = (const float*)d_in[22];
  const float* wdh2_wv = (const float*)d_in[23];
  const float* ln1g = (const float*)d_in[24];
  const float* ln1b = (const float*)d_in[25];
  const float* ln2g = (const float*)d_in[26];
  const float* ln2b = (const float*)d_in[27];
  float* out = (float*)d_out;

  int dev = 0; cudaGetDevice(&dev);
  int sms = 148;
  cudaDeviceGetAttribute(&sms, cudaDevAttrMultiProcessorCount, dev);

  const size_t SMPRE = (size_t)(3456 + 10816 + 528 + 1536 + 104) * sizeof(float); // ~65.8 KB
  const size_t SM1   = (size_t)SM1_FLOATS * sizeof(float);                        // ~216 KB
  const size_t SMDH  = (size_t)(512+1024+400+1024+512+100+768+2368+1536+1536+6976+768+1664+80+6528) * sizeof(float); // ~100.8 KB

  cudaFuncSetAttribute(k_pre,  cudaFuncAttributeMaxDynamicSharedMemorySize, (int)SMPRE);
  cudaFuncSetAttribute(k_edge, cudaFuncAttributeMaxDynamicSharedMemorySize, (int)SM1);
  cudaFuncSetAttribute(k_dh,   cudaFuncAttributeMaxDynamicSharedMemorySize, (int)SMDH);

  k_pre <<<NODES / 32, NT, SMPRE>>>(hV, wev1_ws, wev1_wh);
  k_edge<<<sms, NTE, SM1>>>(hV, hM, maskA,
                            wev1_wh, wev1_ws, wev1_bs, wev1_wv,
                            wev2_wh, wev2_ws, wev2_bs, wev2_wv,
                            wev3_wh, wev3_ws, wev3_bs, wev3_wv,
                            ln1g, ln1b);
  k_dh<<<NODES / 16, DHT, SMDH>>>(wdh1_wh, wdh1_ws, wdh1_bs, wdh1_wv,
                                  wdh2_wh, wdh2_ws, wdh2_bs, wdh2_wv,
                                  ln2g, ln2b, maskV, out);
}

// round 15
// speedup vs baseline: 1.5931x; 1.5931x over previous
#include <cuda_runtime.h>
#include <cuda_pipeline.h>
#include <math.h>
#include <stdint.h>

#define NT 256
#define NTE 512
constexpr int NODES = 4 * 2048;

__device__ float g_hv[NODES * 148];
__device__ float g_sb[NODES * 100];
__device__ float g_vb[NODES * 108];
// tf32-pre-rounded weights: [ws1|ws2|ws3|wdh1_ws|wdh2_ws]
__device__ float g_wc[145700];
#define WC1 0
#define WC2 26500
#define WC3 38100
#define WCD1 49700
#define WCD2 102500

// -------------------- tf32 helpers -----------------------------------------
__device__ __forceinline__ uint32_t f2tf(float x){
  uint32_t r; asm("cvt.rna.tf32.f32 %0, %1;" : "=r"(r) : "f"(x)); return r;
}
__device__ __forceinline__ float rtf(float x){ return __uint_as_float(f2tf(x)); }
__device__ __forceinline__ void mma8(float* c, uint32_t a0,uint32_t a1,uint32_t a2,uint32_t a3,
                                     uint32_t b0,uint32_t b1){
  asm volatile("mma.sync.aligned.m16n8k8.row.col.f32.tf32.tf32.f32 "
    "{%0,%1,%2,%3}, {%4,%5,%6,%7}, {%8,%9}, {%0,%1,%2,%3};"
    : "+f"(c[0]),"+f"(c[1]),"+f"(c[2]),"+f"(c[3])
    : "r"(a0),"r"(a1),"r"(a2),"r"(a3),"r"(b0),"r"(b1));
}

// ---------------- register-tiled GEMM, weights in SMEM ----------------------
template<int NTT,int COLS,int KD,int NROW,int NC,int ARS,int WSTR,bool INITF,bool BIASF,bool RELUF>
__device__ __forceinline__ void gemm_rt(
    const float* __restrict__ A, const float* __restrict__ W,
    const float* __restrict__ initv, const float* __restrict__ bias,
    float* __restrict__ O, const int tid)
{
  constexpr int GPC = NROW / 4;
  constexpr int G   = NC * GPC;
  constexpr int TPG = COLS / 4;
  const int eg = (tid & (TPG - 1)) * 4;
  for (int g = tid / TPG; g < G; g += NTT / TPG) {
    const int c  = g / GPC;
    const int rg = (g - c * GPC) * 4;
    float4 a0, a1, a2, a3;
    if (INITF) {
      const float* iv = initv + c * NROW + rg;
      a0 = make_float4(iv[0], iv[0], iv[0], iv[0]);
      a1 = make_float4(iv[1], iv[1], iv[1], iv[1]);
      a2 = make_float4(iv[2], iv[2], iv[2], iv[2]);
      a3 = make_float4(iv[3], iv[3], iv[3], iv[3]);
    } else {
      a0 = make_float4(0.f,0.f,0.f,0.f); a1 = a0; a2 = a0; a3 = a0;
    }
    const float* ap = A + (size_t)(c * ARS) * COLS + eg;
    const float* wp = W + rg;
    #pragma unroll 4
    for (int k = 0; k < KD; ++k) {
      const float4 av = *(const float4*)(ap + (size_t)k * COLS);
      const float4 wv4 = *(const float4*)(wp + (size_t)k * WSTR);
      a0.x += wv4.x*av.x; a0.y += wv4.x*av.y; a0.z += wv4.x*av.z; a0.w += wv4.x*av.w;
      a1.x += wv4.y*av.x; a1.y += wv4.y*av.y; a1.z += wv4.y*av.z; a1.w += wv4.y*av.w;
      a2.x += wv4.z*av.x; a2.y += wv4.z*av.y; a2.z += wv4.z*av.z; a2.w += wv4.z*av.w;
      a3.x += wv4.w*av.x; a3.y += wv4.w*av.y; a3.z += wv4.w*av.z; a3.w += wv4.w*av.w;
    }
    if (BIASF) {
      const float* bp = bias + c * NROW + rg;
      float b0=bp[0], b1=bp[1], b2=bp[2], b3=bp[3];
      a0.x+=b0; a0.y+=b0; a0.z+=b0; a0.w+=b0;
      a1.x+=b1; a1.y+=b1; a1.z+=b1; a1.w+=b1;
      a2.x+=b2; a2.y+=b2; a2.z+=b2; a2.w+=b2;
      a3.x+=b3; a3.y+=b3; a3.z+=b3; a3.w+=b3;
    }
    if (RELUF) {
      a0.x=fmaxf(a0.x,0.f); a0.y=fmaxf(a0.y,0.f); a0.z=fmaxf(a0.z,0.f); a0.w=fmaxf(a0.w,0.f);
      a1.x=fmaxf(a1.x,0.f); a1.y=fmaxf(a1.y,0.f); a1.z=fmaxf(a1.z,0.f); a1.w=fmaxf(a1.w,0.f);
      a2.x=fmaxf(a2.x,0.f); a2.y=fmaxf(a2.y,0.f); a2.z=fmaxf(a2.z,0.f); a2.w=fmaxf(a2.w,0.f);
      a3.x=fmaxf(a3.x,0.f); a3.y=fmaxf(a3.y,0.f); a3.z=fmaxf(a3.z,0.f); a3.w=fmaxf(a3.w,0.f);
    }
    float* op = O + (size_t)(c * NROW + rg) * COLS + eg;
    *(float4*)(op)          = a0;
    *(float4*)(op + COLS)   = a1;
    *(float4*)(op + 2*COLS) = a2;
    *(float4*)(op + 3*COLS) = a3;
  }
}

// tf32 MMA GEMM, N=100. Weights from g_wc (PRE-ROUNDED -> no cvt). A loads:
// CVA ? cvt : reinterpret (buffers pre-rounded). ROUND: round epilogue stores.
template<int NTT,int NQ,int KPAD,int KREAL,int CH,int ASTR,int OSTR,int WSRC,int ISTR,
         bool INITF,bool RELUF,bool CVA,bool ROUND>
__device__ __forceinline__ void gemm_mma(
    const float* __restrict__ As, const float* __restrict__ Wg,
    const float* __restrict__ initv, const float* __restrict__ bias,
    float* __restrict__ OT, float* __restrict__ wbuf, const int tid)
{
  constexpr int WS  = 104;
  constexpr int NCH = KPAD / CH;
  constexpr int T   = 13;
  constexpr int JMAX = (T + NQ - 1) / NQ;
  static_assert(KPAD % CH == 0 && CH % 8 == 0, "pad");
  const int lane = tid & 31;
  const int warp = tid >> 5;
  const int g  = lane >> 2;
  const int tq = lane & 3;
  const int mt = warp / NQ;
  const int q  = warp % NQ;
  float acc[JMAX][4];
  #pragma unroll
  for (int j=0;j<JMAX;++j){acc[j][0]=0.f;acc[j][1]=0.f;acc[j][2]=0.f;acc[j][3]=0.f;}

  auto stage = [&](int ch){
    float* db = wbuf + (ch & 1) * (CH * WS);
    const int base = ch * CH;
    for (int i = tid; i < CH*25; i += NTT) {
      int r = i / 25, c4 = i - r*25;
      int kr = base + r;
      if (kr < KREAL) __pipeline_memcpy_async(db + r*WS + c4*4, Wg + (size_t)kr*WSRC + c4*4, 16);
      else { float4 z = make_float4(0.f,0.f,0.f,0.f); *(float4*)(db + r*WS + c4*4) = z; }
    }
    __pipeline_commit();
  };
  stage(0);
  for (int ch = 0; ch < NCH; ++ch) {
    __pipeline_wait_prior(0);
    __syncthreads();
    if (ch + 1 < NCH) stage(ch + 1);
    const float* wb = wbuf + (ch & 1) * (CH * WS);
    const float* arow = As + (size_t)(mt*16 + g) * ASTR + ch*CH;
    #pragma unroll
    for (int k8 = 0; k8 < CH/8; ++k8) {
      const float* ar = arow + k8*8;
      uint32_t a0 = CVA ? f2tf(ar[tq])            : __float_as_uint(ar[tq]);
      uint32_t a1 = CVA ? f2tf(ar[8*ASTR + tq])   : __float_as_uint(ar[8*ASTR + tq]);
      uint32_t a2 = CVA ? f2tf(ar[tq + 4])        : __float_as_uint(ar[tq + 4]);
      uint32_t a3 = CVA ? f2tf(ar[8*ASTR + tq+4]) : __float_as_uint(ar[8*ASTR + tq + 4]);
      const float* wrow = wb + (k8*8 + tq)*WS + g;
      #pragma unroll
      for (int j = 0; j < JMAX; ++j) {
        int tile = q + NQ*j;
        if (tile < T) {
          const float* wr = wrow + tile*8;
          uint32_t b0 = __float_as_uint(wr[0]);
          uint32_t b1 = __float_as_uint(wr[4*WS]);
          mma8(acc[j], a0,a1,a2,a3, b0,b1);
        }
      }
    }
  }
  const int e0 = mt*16 + g;
  const float* iv = INITF ? (initv + (e0 >> 5) * ISTR) : nullptr;
  #pragma unroll
  for (int j = 0; j < JMAX; ++j) {
    int tile = q + NQ*j;
    if (tile < T) {
      int mb = tile*8 + 2*tq;
      #pragma unroll
      for (int hf = 0; hf < 2; ++hf) {
        int m = mb + hf;
        if (m < 100) {
          float add = (INITF ? iv[m] : 0.f) + bias[m];
          float v0 = acc[j][hf]   + add;
          float v1 = acc[j][2+hf] + add;
          if (RELUF) { v0 = fmaxf(v0, 0.f); v1 = fmaxf(v1, 0.f); }
          if (ROUND) { v0 = rtf(v0); v1 = rtf(v1); }
          OT[(size_t)e0 * OSTR + m]     = v0;
          OT[(size_t)(e0+8) * OSTR + m] = v1;
        }
      }
    }
  }
}

// tf32 MMA GEMM, wide N (weights pre-rounded; CVA/ROUND as above)
template<int NTT,int NQ,int KPAD,int KREAL,int CH,int ASTR,int OSTR,int N,
         bool RELUF,bool CVA,bool ROUND>
__device__ __forceinline__ void gemm_mmaW(
    const float* __restrict__ As, const float* __restrict__ Wg,
    const float* __restrict__ bias,
    float* __restrict__ OT, float* __restrict__ wbuf, const int tid)
{
  constexpr int WS  = N + 8;
  constexpr int NCH = KPAD / CH;
  constexpr int T   = N / 8;
  constexpr int JMAX = (T + NQ - 1) / NQ;
  static_assert(KPAD % CH == 0 && CH % 8 == 0 && N % 8 == 0, "pad");
  const int lane = tid & 31;
  const int warp = tid >> 5;
  const int g  = lane >> 2;
  const int tq = lane & 3;
  const int mt = warp / NQ;
  const int q  = warp % NQ;
  float acc[JMAX][4];
  #pragma unroll
  for (int j=0;j<JMAX;++j){acc[j][0]=0.f;acc[j][1]=0.f;acc[j][2]=0.f;acc[j][3]=0.f;}

  auto stage = [&](int ch){
    float* db = wbuf + (ch & 1) * (CH * WS);
    const int base = ch * CH;
    constexpr int Q4 = N / 4;
    for (int i = tid; i < CH*Q4; i += NTT) {
      int r = i / Q4, c4 = i - r*Q4;
      int kr = base + r;
      if (kr < KREAL) __pipeline_memcpy_async(db + r*WS + c4*4, Wg + (size_t)kr*N + c4*4, 16);
      else { float4 z = make_float4(0.f,0.f,0.f,0.f); *(float4*)(db + r*WS + c4*4) = z; }
    }
    __pipeline_commit();
  };
  stage(0);
  for (int ch = 0; ch < NCH; ++ch) {
    __pipeline_wait_prior(0);
    __syncthreads();
    if (ch + 1 < NCH) stage(ch + 1);
    const float* wb = wbuf + (ch & 1) * (CH * WS);
    const float* arow = As + (size_t)(mt*16 + g) * ASTR + ch*CH;
    #pragma unroll
    for (int k8 = 0; k8 < CH/8; ++k8) {
      const float* ar = arow + k8*8;
      uint32_t a0 = CVA ? f2tf(ar[tq])            : __float_as_uint(ar[tq]);
      uint32_t a1 = CVA ? f2tf(ar[8*ASTR + tq])   : __float_as_uint(ar[8*ASTR + tq]);
      uint32_t a2 = CVA ? f2tf(ar[tq + 4])        : __float_as_uint(ar[tq + 4]);
      uint32_t a3 = CVA ? f2tf(ar[8*ASTR + tq+4]) : __float_as_uint(ar[8*ASTR + tq + 4]);
      const float* wrow = wb + (k8*8 + tq)*WS + g;
      #pragma unroll
      for (int j = 0; j < JMAX; ++j) {
        int tile = q + NQ*j;
        if (tile < T) {
          const float* wr = wrow + tile*8;
          uint32_t b0 = __float_as_uint(wr[0]);
          uint32_t b1 = __float_as_uint(wr[4*WS]);
          mma8(acc[j], a0,a1,a2,a3, b0,b1);
        }
      }
    }
  }
  const int e0 = mt*16 + g;
  #pragma unroll
  for (int j = 0; j < JMAX; ++j) {
    int tile = q + NQ*j;
    if (tile < T) {
      int mb = tile*8 + 2*tq;
      #pragma unroll
      for (int hf = 0; hf < 2; ++hf) {
        int m = mb + hf;
        float b = bias[m];
        float v0 = acc[j][hf]   + b;
        float v1 = acc[j][2+hf] + b;
        if (RELUF) { v0 = fmaxf(v0, 0.f); v1 = fmaxf(v1, 0.f); }
        if (ROUND) { v0 = rtf(v0); v1 = rtf(v1); }
        OT[(size_t)e0 * OSTR + m]     = v0;
        OT[(size_t)(e0+8) * OSTR + m] = v1;
      }
    }
  }
}

// ------------- K-1: pre-round all s-GEMM weights into g_wc ------------------
__global__ __launch_bounds__(NT)
void k_wcvt(const float* __restrict__ w1, const float* __restrict__ w2,
            const float* __restrict__ w3, const float* __restrict__ wd1,
            const float* __restrict__ wd2)
{
  int i = blockIdx.x * NT + threadIdx.x;
  float v;
  if      (i < 26500)  v = w1[i];
  else if (i < 38100)  v = w2[i - 26500];
  else if (i < 49700)  v = w3[i - 38100];
  else if (i < 102500) v = wd1[i - 49700];
  else if (i < 145700) v = wd2[i - 102500];
  else return;
  g_wc[i] = rtf(v);
}

// ------------ K0: hoisted per-node partials (32-node MMA tiles) -------------
__global__ __launch_bounds__(NT)
void k_pre(const float* __restrict__ hV, const float* __restrict__ wh1)
{
  extern __shared__ float sm[];
  float* As  = sm;            // [32][108]
  float* WB  = As + 3456;     // wbuf
  float* WH  = WB + 10816;    // 528
  float* HVv = WH + 528;      // [32][48]
  float* ZB  = HVv + 1536;    // 104
  const int tid = threadIdx.x;
  const int n0 = blockIdx.x * 32;

  for (int i = tid; i < 528; i += NT) WH[i] = wh1[i];
  for (int i = tid; i < 104; i += NT) ZB[i] = 0.f;
  for (int idx = tid; idx < 32 * 8; idx += NT) {
    int e = idx >> 3, j = idx & 7;
    As[e * 108 + 100 + j] = 0.f;
  }
  for (int idx = tid; idx < 32 * 148; idx += NT) {
    int e = idx / 148, r = idx - e * 148;
    float v = hV[(size_t)(n0 + e) * 148 + r];
    if (r < 48) HVv[e * 48 + r] = v;
    else        As[e * 108 + (r - 48)] = rtf(v);
  }
  __syncthreads();
  gemm_mma<NT,4,104,100,104,108,100,100,0,false,false,false,false>(
      As, g_wc + WC1, nullptr, ZB, g_sb + (size_t)n0 * 100, WB, tid);
  for (int t = tid; t < 32 * 108; t += NT) {
    int e = t / 108, u = t - e * 108;
    int c = u / 36, h = u - c * 36;
    float acc = 0.f;
    if (h < 33) {
      #pragma unroll
      for (int i = 0; i < 16; ++i) acc += HVv[e * 48 + c * 16 + i] * WH[i * 33 + h];
    }
    g_vb[(size_t)(n0 + e) * 108 + u] = acc;
  }
}

// --------------- K1: edges + mean + LN1 (node PAIRS, 64-edge tiles) --------
#define O_WH1P 0
#define O_WV1  1188
#define O_BS1  1716
#define O_WH2  1816
#define O_WV2  2072
#define O_BS2  2328
#define O_WH3  2428
#define O_WV3  2684
#define O_BS3  2940
#define O_LG1  3040
#define O_LB1  3140
#define O_HS   3240
#define O_MK   3536
#define O_SB   3600
#define O_VB   3800
#define O_VC1  4016
#define O_SC1T 7280
#define O_VHX  18288
#define O_BFAT 25200
#define O_VOA  33136
#define O_DH   36208
#define O_MISC 36504
#define O_WBUF 36520   /* 2*56*104 = 11648 */
#define SM1_FLOATS 48168

__global__ __launch_bounds__(NTE, 1)
void k_edge(const float* __restrict__ hV, const float* __restrict__ hM,
            const int* __restrict__ maskA,
            const float* __restrict__ wh1,
            const float* __restrict__ bs1, const float* __restrict__ wv1,
            const float* __restrict__ wh2,
            const float* __restrict__ bs2, const float* __restrict__ wv2,
            const float* __restrict__ wh3,
            const float* __restrict__ bs3, const float* __restrict__ wv3,
            const float* __restrict__ ln1g, const float* __restrict__ ln1b)
{
  extern __shared__ float sm[];
  float* WH1P = sm + O_WH1P;
  float* WV1  = sm + O_WV1;
  float* BS1s = sm + O_BS1;
  float* WH2s = sm + O_WH2;
  float* WV2s = sm + O_WV2;
  float* BS2s = sm + O_BS2;
  float* WH3s = sm + O_WH3;
  float* WV3s = sm + O_WV3;
  float* BS3s = sm + O_BS3;
  float* LG1  = sm + O_LG1;
  float* LB1  = sm + O_LB1;
  float* HS   = sm + O_HS;
  float* MK   = sm + O_MK;
  float* SB   = sm + O_SB;
  float* VB   = sm + O_VB;
  float* VC1  = sm + O_VC1;
  float* SC1T = sm + O_SC1T;
  float* VHX  = sm + O_VHX;
  float* BFAT = sm + O_BFAT;
  float* BFBT = sm + O_SC1T;   // alias
  float* VOA  = sm + O_VOA;
  float* DH   = sm + O_DH;
  float* MISC = sm + O_MISC;
  float* WBUF = sm + O_WBUF;
  float* EBV  = sm + O_VHX;    // vector staging [2][30][51]
  const int tid = threadIdx.x;

  for (int i = tid; i < 1188; i += NTE) { int r = i / 36, c = i - r * 36; WH1P[i] = (c < 33) ? wh1[r * 33 + c] : 0.f; }
  for (int i = tid; i < 528;  i += NTE) WV1[i]  = wv1[i];
  for (int i = tid; i < 100;  i += NTE) { BS1s[i] = bs1[i]; BS2s[i] = bs2[i]; BS3s[i] = bs3[i]; LG1[i] = ln1g[i]; LB1[i] = ln1b[i]; }
  for (int i = tid; i < 256;  i += NTE) { WH2s[i] = wh2[i]; WV2s[i] = wv2[i]; WH3s[i] = wh3[i]; WV3s[i] = wv3[i]; }
  for (int i = tid; i < 3264;  i += NTE) VC1[i]  = 0.f;
  for (int i = tid; i < 11008; i += NTE) SC1T[i] = 0.f;
  for (int i = tid; i < 7936;  i += NTE) BFAT[i] = 0.f;
  for (int i = tid; i < 11648; i += NTE) WBUF[i] = 0.f;
  __syncthreads();

  for (int pair = blockIdx.x; pair < NODES / 2; pair += gridDim.x) {
    const float* mp = hM + (size_t)pair * 10980;
    for (int idx = tid; idx < 2 * 30 * 132; idx += NTE) {
      int n = idx / 3960, rem = idx - n * 3960;
      int e = rem / 132, j = rem - e * 132;
      SC1T[(size_t)(n * 32 + e) * 172 + j] = rtf(mp[n * 5490 + e * 183 + 51 + j]);
    }
    for (int idx = tid; idx < 2 * 30 * 51; idx += NTE) {
      int n = idx / 1530, rem = idx - n * 1530;
      EBV[idx] = mp[n * 5490 + (rem / 51) * 183 + (rem % 51)];
    }
    for (int t = tid; t < 296; t += NTE) HS[t] = hV[(size_t)pair * 296 + t];
    for (int t = tid; t < 200; t += NTE) SB[t] = g_sb[(size_t)pair * 200 + t];
    for (int t = tid; t < 216; t += NTE) VB[t] = g_vb[(size_t)pair * 216 + t];
    for (int t = tid; t < 64;  t += NTE) {
      int el = t & 31;
      MK[t] = (el < 30) ? (float)maskA[(size_t)(2 * pair + (t >> 5)) * 30 + el] : 0.f;
    }
    __syncthreads();
    for (int idx = tid; idx < 51 * 64; idx += NTE) {
      int j = idx >> 6, e = idx & 63;
      int n = e >> 5, el = e & 31;
      if (el < 30) VC1[j * 64 + e] = EBV[n * 1530 + el * 51 + j];
    }
    __syncthreads();
    gemm_rt<NTE,64,17,36,3,17,36,false,false,false>(VC1, WH1P + 16 * 36, nullptr, nullptr, VHX, tid);
    __syncthreads();
    for (int idx = tid; idx < 108 * 64; idx += NTE) {
      int r = idx >> 6, e = idx & 63;
      VHX[idx] += VB[(e >> 5) * 108 + r];
    }
    __syncthreads();
    for (int t = tid; t < 33 * 64; t += NTE) {
      int h = t >> 6, e = t & 63;
      float a = VHX[h*64+e], b = VHX[(36+h)*64+e], c2 = VHX[(72+h)*64+e];
      SC1T[(size_t)e * 172 + 132 + h] = rtf(sqrtf(fmaxf(a*a + b*b + c2*c2, 1e-8f)));
    }
    gemm_rt<NTE,64,33,16,3,36,16,false,false,false>(VHX, WV1, nullptr, nullptr, VOA, tid);
    gemm_mma<NTE,4,168,165,56,172,124,100,100,true,true,false,true>(SC1T, g_wc + WC1 + 10000, SB, BS1s, BFAT, WBUF, tid);
    for (int t = tid; t < 16 * 64; t += NTE) {
      int o = t >> 6, e = t & 63;
      float a = VOA[o*64+e], b = VOA[(16+o)*64+e], c2 = VOA[(32+o)*64+e];
      float n = sqrtf(fmaxf(a*a + b*b + c2*c2, 1e-8f));
      float gt = 1.f / (1.f + expf(-n));
      VOA[o*64+e] = a*gt; VOA[(16+o)*64+e] = b*gt; VOA[(32+o)*64+e] = c2*gt;
    }
    __syncthreads();
    gemm_rt<NTE,64,16,16,3,16,16,false,false,false>(VOA, WH2s, nullptr, nullptr, VHX, tid);
    __syncthreads();
    for (int t = tid; t < 16 * 64; t += NTE) {
      int h = t >> 6, e = t & 63;
      float a = VHX[h*64+e], b = VHX[(16+h)*64+e], c2 = VHX[(32+h)*64+e];
      BFAT[(size_t)e * 124 + 100 + h] = rtf(sqrtf(fmaxf(a*a + b*b + c2*c2, 1e-8f)));
    }
    gemm_rt<NTE,64,16,16,3,16,16,false,false,false>(VHX, WV2s, nullptr, nullptr, VOA, tid);
    gemm_mma<NTE,4,120,116,40,124,124,100,0,false,true,false,true>(BFAT, g_wc + WC2, nullptr, BS2s, BFBT, WBUF, tid);
    for (int t = tid; t < 16 * 64; t += NTE) {
      int o = t >> 6, e = t & 63;
      float a = VOA[o*64+e], b = VOA[(16+o)*64+e], c2 = VOA[(32+o)*64+e];
      float n = sqrtf(fmaxf(a*a + b*b + c2*c2, 1e-8f));
      float gt = 1.f / (1.f + expf(-n));
      VOA[o*64+e] = a*gt; VOA[(16+o)*64+e] = b*gt; VOA[(32+o)*64+e] = c2*gt;
    }
    __syncthreads();
    gemm_rt<NTE,64,16,16,3,16,16,false,false,false>(VOA, WH3s, nullptr, nullptr, VHX, tid);
    __syncthreads();
    for (int t = tid; t < 16 * 64; t += NTE) {
      int h = t >> 6, e = t & 63;
      float a = VHX[h*64+e], b = VHX[(16+h)*64+e], c2 = VHX[(32+h)*64+e];
      BFBT[(size_t)e * 124 + 100 + h] = rtf(sqrtf(fmaxf(a*a + b*b + c2*c2, 1e-8f)));
    }
    gemm_rt<NTE,64,16,16,3,16,16,false,false,false>(VHX, WV3s, nullptr, nullptr, VOA, tid);
    gemm_mma<NTE,4,120,116,40,124,124,100,0,false,false,false,false>(BFBT, g_wc + WC3, nullptr, BS3s, BFAT, WBUF, tid);
    __syncthreads();
    for (int t = tid; t < 296; t += NTE) {
      int n = t / 148, r = t - n * 148;
      float acc = 0.f;
      if (r < 48) {
        #pragma unroll
        for (int ee = 0; ee < 32; ++ee) {
          int e = n * 32 + ((ee + r) & 31);
          acc += MK[e] * VOA[r * 64 + e];
        }
      } else {
        int rr = r - 48;
        #pragma unroll 6
        for (int e = 0; e < 30; ++e) acc += MK[n * 32 + e] * BFAT[(size_t)(n * 32 + e) * 124 + rr];
      }
      DH[t] = HS[t] + acc * (1.f / 30.f);
    }
    __syncthreads();
    if (tid < 64) {
      const int w = tid >> 5, lane = tid & 31;
      const float* D = DH + w * 148;
      float vm = 0.f;
      if (lane < 16) { float a = D[lane], b = D[16+lane], c2 = D[32+lane]; vm = fmaxf(a*a + b*b + c2*c2, 1e-8f); }
      #pragma unroll
      for (int o = 16; o; o >>= 1) vm += __shfl_xor_sync(0xffffffffu, vm, o);
      float s0 = D[48+lane], s1 = D[80+lane], s2v = D[112+lane];
      float s3v = (lane < 4) ? D[144+lane] : 0.f;
      float p = s0 + s1 + s2v + s3v;
      #pragma unroll
      for (int o = 16; o; o >>= 1) p += __shfl_xor_sync(0xffffffffu, p, o);
      float mu = p * 0.01f;
      float d0 = s0-mu, d1 = s1-mu, d2 = s2v-mu;
      float q = d0*d0 + d1*d1 + d2*d2;
      if (lane < 4) { float d3 = s3v - mu; q += d3*d3; }
      #pragma unroll
      for (int o = 16; o; o >>= 1) q += __shfl_xor_sync(0xffffffffu, q, o);
      if (lane == 0) {
        MISC[w*4+0] = rsqrtf(vm * (1.f/16.f));
        MISC[w*4+1] = mu;
        MISC[w*4+2] = rsqrtf(q * 0.01f + 1e-3f);
      }
    }
    __syncthreads();
    for (int t = tid; t < 296; t += NTE) {
      int n = t / 148, r = t - n * 148;
      float v = DH[t];
      if (r < 48) v = v * MISC[n*4];
      else { int j = r - 48; v = (v - MISC[n*4+1]) * MISC[n*4+2] * LG1[j] + LB1[j]; }
      g_hv[(size_t)pair * 296 + t] = v;
    }
    __syncthreads();
  }
}

// -------------------- K2: fused dh1+dh2+LN2 (16-node tiles, 512 thr) -------
#define DHT 512
__global__ __launch_bounds__(DHT, 2)
void k_dh(const float* __restrict__ wh1,
          const float* __restrict__ bs1, const float* __restrict__ wv1,
          const float* __restrict__ wh2,
          const float* __restrict__ bs2, const float* __restrict__ wv2,
          const float* __restrict__ ln2g, const float* __restrict__ ln2b,
          const int* __restrict__ maskV, float* __restrict__ out)
{
  extern __shared__ float sm[];
  float* WHs1 = sm;             // 512
  float* WVs1 = WHs1 + 512;     // 1024
  float* BSs1 = WVs1 + 1024;    // 400
  float* WHs2 = BSs1 + 400;     // 1024
  float* WVs2 = WHs2 + 1024;    // 512
  float* BSs2 = WVs2 + 512;     // 100
  float* VC1  = BSs2 + 100;     // 768
  float* SC1T = VC1 + 768;      // 2368
  float* VH   = SC1T + 2368;    // 1536
  float* VOd1 = VH + 1536;      // 1536
  float* SCT  = VOd1 + 1536;    // 6976
  float* VO2  = SCT + 6976;     // 768
  float* OT   = VO2 + 768;      // 1664
  float* ST   = OT + 1664;      // 80
  float* WBUF = ST + 80;        // 6528
  float* RES  = WBUF;           // [148][17] alias after MMAs done
  const int tid = threadIdx.x;
  const int n0 = blockIdx.x * 16;

  for (int i = tid; i < 512;  i += DHT) WHs1[i] = wh1[i];
  for (int i = tid; i < 1024; i += DHT) WVs1[i] = wv1[i];
  for (int i = tid; i < 400;  i += DHT) BSs1[i] = bs1[i];
  for (int i = tid; i < 1024; i += DHT) WHs2[i] = wh2[i];
  for (int i = tid; i < 512;  i += DHT) WVs2[i] = wv2[i];
  for (int i = tid; i < 100;  i += DHT) BSs2[i] = bs2[i];
  if (tid < 16) ST[48 + tid] = (float)maskV[n0 + tid];
  for (int idx = tid; idx < 48 * 16; idx += DHT) {
    int r = idx >> 4, e = idx & 15;
    VC1[r * 16 + e] = g_hv[(size_t)(n0 + e) * 148 + r];
  }
  for (int idx = tid; idx < 16 * 148; idx += DHT) {
    int e = idx / 148, j = idx - e * 148;
    SC1T[idx] = (j < 100) ? rtf(g_hv[(size_t)(n0 + e) * 148 + 48 + j]) : 0.f;
  }
  __syncthreads();
  gemm_rt<DHT,16,16,32,3,16,32,false,false,false>(VC1, WHs1, nullptr, nullptr, VH, tid);
  __syncthreads();
  {
    int h = tid >> 4, e = tid & 15;
    float a = VH[h*16+e], b = VH[(32+h)*16+e], c2 = VH[(64+h)*16+e];
    SC1T[e * 148 + 100 + h] = rtf(sqrtf(fmaxf(a*a + b*b + c2*c2, 1e-8f)));
  }
  gemm_rt<DHT,16,32,32,3,32,32,false,false,false>(VH, WVs1, nullptr, nullptr, VOd1, tid);
  gemm_mmaW<DHT,16,144,132,8,148,436,400,true,false,true>(SC1T, g_wc + WCD1, BSs1, SCT, WBUF, tid);
  __syncthreads();
  {
    int o = tid >> 4, e = tid & 15;
    float a = VOd1[o*16+e], b = VOd1[(32+o)*16+e], c2 = VOd1[(64+o)*16+e];
    float n = sqrtf(fmaxf(a*a + b*b + c2*c2, 1e-8f));
    float gt = 1.f / (1.f + expf(-n));
    VOd1[o*16+e] = a*gt; VOd1[(32+o)*16+e] = b*gt; VOd1[(64+o)*16+e] = c2*gt;
  }
  __syncthreads();
  gemm_rt<DHT,16,32,32,3,32,32,false,false,false>(VOd1, WHs2, nullptr, nullptr, VH, tid);
  __syncthreads();
  {
    int h = tid >> 4, e = tid & 15;
    float a = VH[h*16+e], b = VH[(32+h)*16+e], c2 = VH[(64+h)*16+e];
    SCT[e * 436 + 400 + h] = rtf(sqrtf(fmaxf(a*a + b*b + c2*c2, 1e-8f)));
  }
  gemm_rt<DHT,16,32,16,3,32,16,false,false,false>(VH, WVs2, nullptr, nullptr, VO2, tid);
  gemm_mma<DHT,16,432,432,24,436,104,100,0,false,false,false,false>(SCT, g_wc + WCD2, nullptr, BSs2, OT, WBUF, tid);
  __syncthreads();
  for (int idx = tid; idx < 148 * 16; idx += DHT) {
    int r = idx >> 4, e = idx & 15;
    float add = (r < 48) ? VO2[r * 16 + e] : OT[e * 104 + (r - 48)];
    RES[r * 17 + e] = g_hv[(size_t)(n0 + e) * 148 + r] + add;
  }
  __syncthreads();
  if (tid < 16) {
    const int e = tid;
    float vm = 0.f;
    #pragma unroll
    for (int i = 0; i < 16; ++i) {
      float a = RES[i*17+e], b = RES[(16+i)*17+e], c2 = RES[(32+i)*17+e];
      vm += fmaxf(a*a + b*b + c2*c2, 1e-8f);
    }
    float mu = 0.f;
    #pragma unroll 4
    for (int j = 0; j < 100; ++j) mu += RES[(48+j)*17+e];
    mu *= 0.01f;
    float var = 0.f;
    #pragma unroll 4
    for (int j = 0; j < 100; ++j) { float d = RES[(48+j)*17+e] - mu; var += d*d; }
    var *= 0.01f;
    ST[e]    = rsqrtf(vm * (1.f/16.f));
    ST[16+e] = mu;
    ST[32+e] = rsqrtf(var + 1e-3f);
  }
  __syncthreads();
  for (int idx = tid; idx < 16 * 148; idx += DHT) {
    int e = idx / 148, r = idx - e * 148;
    float v = RES[r * 17 + e];
    if (r < 48) v = v * ST[e];
    else { int j = r - 48; v = (v - ST[16+e]) * ST[32+e] * ln2g[j] + ln2b[j]; }
    out[(size_t)(n0 + e) * 148 + r] = ST[48 + e] * v;
  }
}

// ---------------------------------------------------------------------------
extern "C" void kernel_launch(void* const* d_in, const int* in_sizes, int n_in,
                              void* d_out, int out_size)
{
  const float* hV      = (const float*)d_in[0];
  const float* hM      = (const float*)d_in[1];
  const int*   maskV   = (const int*)  d_in[2];
  const int*   maskA   = (const int*)  d_in[3];
  const float* wev1_wh = (const float*)d_in[4];
  const float* wev1_ws = (const float*)d_in[5];
  const float* wev1_bs = (const float*)d_in[6];
  const float* wev1_wv = (const float*)d_in[7];
  const float* wev2_wh = (const float*)d_in[8];
  const float* wev2_ws = (const float*)d_in[9];
  const float* wev2_bs = (const float*)d_in[10];
  const float* wev2_wv = (const float*)d_in[11];
  const float* wev3_wh = (const float*)d_in[12];
  const float* wev3_ws = (const float*)d_in[13];
  const float* wev3_bs = (const float*)d_in[14];
  const float* wev3_wv = (const float*)d_in[15];
  const float* wdh1_wh = (const float*)d_in[16];
  const float* wdh1_ws = (const float*)d_in[17];
  const float* wdh1_bs = (const float*)d_in[18];
  const float* wdh1_wv = (const float*)d_in[19];
  const float* wdh2_wh = (const float*)d_in[20];
  const float* wdh2_ws = (const float*)d_in[21];
  const float* wdh2_bs = (const float*)d_in[22];
  const float* wdh2_wv = (const float*)d_in[23];
  const float* ln1g = (const float*)d_in[24];
  const float* ln1b = (const float*)d_in[25];
  const float* ln2g = (const float*)d_in[26];
  const float* ln2b = (const float*)d_in[27];
  float* out = (float*)d_out;

  int dev = 0; cudaGetDevice(&dev);
  int sms = 148;
  cudaDeviceGetAttribute(&sms, cudaDevAttrMultiProcessorCount, dev);

  const size_t SMPRE = (size_t)(3456 + 10816 + 528 + 1536 + 104) * sizeof(float); // ~65.8 KB
  const size_t SM1   = (size_t)SM1_FLOATS * sizeof(float);                        // ~188 KB
  const size_t SMDH  = (size_t)(512+1024+400+1024+512+100+768+2368+1536+1536+6976+768+1664+80+6528) * sizeof(float); // ~100.8 KB

  cudaFuncSetAttribute(k_pre,  cudaFuncAttributeMaxDynamicSharedMemorySize, (int)SMPRE);
  cudaFuncSetAttribute(k_edge, cudaFuncAttributeMaxDynamicSharedMemorySize, (int)SM1);
  cudaFuncSetAttribute(k_dh,   cudaFuncAttributeMaxDynamicSharedMemorySize, (int)SMDH);

  k_wcvt<<<(145700 + NT - 1) / NT, NT>>>(wev1_ws, wev2_ws, wev3_ws, wdh1_ws, wdh2_ws);
  k_pre <<<NODES / 32, NT, SMPRE>>>(hV, wev1_wh);
  k_edge<<<sms, NTE, SM1>>>(hV, hM, maskA,
                            wev1_wh, wev1_bs, wev1_wv,
                            wev2_wh, wev2_bs, wev2_wv,
                            wev3_wh, wev3_bs, wev3_wv,
                            ln1g, ln1b);
  k_dh<<<NODES / 16, DHT, SMDH>>>(wdh1_wh, wdh1_bs, wdh1_wv,
                                  wdh2_wh, wdh2_bs, wdh2_wv,
                                  ln2g, ln2b, maskV, out);
}